// round 3
// baseline (speedup 1.0000x reference)
#include <cuda_runtime.h>
#include <cuda_bf16.h>
#include <cstdint>

// Problem constants
#define Bsz   16384
#define INPUT 512
#define HID   1024
#define MEM   1152
#define SQ    48

// GEMM tiling
#define BM 128
#define BN 128
#define BK 32
#define BKP 36                 // padded K stride in floats
#define ATILE (BM*BKP)         // 4608 floats
#define STAGE_F (2*ATILE)
#define NSTAGE 3
#define SMEM_BYTES (NSTAGE*STAGE_F*4)   // 110592 B

#define KT1 (2688/BK)          // 84
#define KT2 (2176/BK)          // 68

// Scratch
__device__ float g_c[(size_t)Bsz*2688];     // tf32-rounded [input|h_prev|m_prev] (176 MB)
__device__ float g_w1[(size_t)HID*2688];    // tf32-rounded W_h (11 MB)
__device__ float g_h[(size_t)Bsz*HID];      // tf32-rounded h (64 MB)
__device__ float g_y[(size_t)Bsz*HID];      // pre-LN GEMM1 output (64 MB)
__device__ float g_u[(size_t)Bsz*256];      // stage-2 GEMM output, stride 256 (16 MB)
__device__ float g_wcat[256*2176];          // packed+rounded [W_a;W_b;W_va;W_vb]
__device__ float g_bcat[256];

// ---------------------------------------------------------------------------
__device__ __forceinline__ float tfr(float x) {
    uint32_t r;
    asm("cvt.rna.tf32.f32 %0, %1;" : "=r"(r) : "f"(x));
    return __uint_as_float(r);
}

__device__ __forceinline__ void mma8(float* c, const uint32_t* a, const uint32_t* b) {
    asm volatile(
        "mma.sync.aligned.m16n8k8.row.col.f32.tf32.tf32.f32 "
        "{%0,%1,%2,%3}, {%4,%5,%6,%7}, {%8,%9}, {%0,%1,%2,%3};\n"
        : "+f"(c[0]), "+f"(c[1]), "+f"(c[2]), "+f"(c[3])
        : "r"(a[0]), "r"(a[1]), "r"(a[2]), "r"(a[3]), "r"(b[0]), "r"(b[1]));
}

__device__ __forceinline__ void cp_async16(float* s, const float* g) {
    uint32_t sa = (uint32_t)__cvta_generic_to_shared(s);
    asm volatile("cp.async.cg.shared.global [%0], [%1], 16;\n" :: "r"(sa), "l"(g));
}
#define CP_COMMIT() asm volatile("cp.async.commit_group;\n" ::: "memory")
#define CP_WAIT2()  asm volatile("cp.async.wait_group 2;\n" ::: "memory")

#define FU(x) __float_as_uint(x)
#define COMP(v, i) (((const float*)&(v))[i])

// ---------------------------------------------------------------------------
// Round+concat inputs into g_c : [input(512) | h_prev(1024) | m_prev(1152)]
__global__ __launch_bounds__(256)
void round_concat_kernel(const float4* __restrict__ X, const float4* __restrict__ H,
                         const float4* __restrict__ M) {
    int idx = blockIdx.x * 256 + threadIdx.x;       // one float4, total 16384*672
    int b = idx / 672, c = idx - b * 672;
    float4 v;
    if (c < 128)      v = X[(size_t)b * 128 + c];
    else if (c < 384) v = H[(size_t)b * 256 + (c - 128)];
    else              v = M[(size_t)b * 288 + (c - 384)];
    v.x = tfr(v.x); v.y = tfr(v.y); v.z = tfr(v.z); v.w = tfr(v.w);
    ((float4*)g_c)[idx] = v;
}

// Round W_h into g_w1
__global__ __launch_bounds__(256)
void round_wh_kernel(const float4* __restrict__ W) {
    int idx = blockIdx.x * 256 + threadIdx.x;       // total 1024*672
    float4 v = W[idx];
    v.x = tfr(v.x); v.y = tfr(v.y); v.z = tfr(v.z); v.w = tfr(v.w);
    ((float4*)g_w1)[idx] = v;
}

// Pack + round small weights into 256 x 2176 (+ biases)
__global__ void pack_w_kernel(const float* Wa, const float* ba,
                              const float* Wb, const float* bb,
                              const float* Wva, const float* bva,
                              const float* Wvb, const float* bvb) {
    int idx = blockIdx.x * blockDim.x + threadIdx.x;
    const int total = 196 * 2176;
    if (idx < total) {
        int n = idx / 2176, k = idx - n * 2176;
        const float* src; int r;
        if (n < 2)        { src = Wa;  r = n; }
        else if (n < 4)   { src = Wb;  r = n - 2; }
        else if (n < 100) { src = Wva; r = n - 4; }
        else              { src = Wvb; r = n - 100; }
        g_wcat[n * 2176 + k] = tfr(src[(size_t)r * 2176 + k]);
    }
    if (idx < 196) {
        int n = idx;
        float v;
        if (n < 2)        v = ba[n];
        else if (n < 4)   v = bb[n - 2];
        else if (n < 100) v = bva[n - 4];
        else              v = bvb[n - 100];
        g_bcat[n] = v;
    }
}

// ---------------------------------------------------------------------------
// Shared GEMM compute core: 128x128 CTA tile, 4 warps of 64x64, pre-rounded tf32.
// k-permutation: mma k-slot (chunk j, lane lc, slot s) <- smem col 8*lc + 2*j + s.
// Dot products are k-permutation invariant; A and B use the same mapping.
#define GEMM_CORE(KT)                                                          \
    const int warp = tid >> 5, lane = tid & 31;                                \
    const int wm = warp >> 1, wn = warp & 1;                                   \
    const int lr = lane >> 2, lc = lane & 3;                                   \
    float acc[4][8][4];                                                        \
    _Pragma("unroll")                                                          \
    for (int i = 0; i < 4; i++)                                                \
        _Pragma("unroll")                                                      \
        for (int j = 0; j < 8; j++) {                                          \
            acc[i][j][0] = 0.f; acc[i][j][1] = 0.f;                            \
            acc[i][j][2] = 0.f; acc[i][j][3] = 0.f;                            \
        }                                                                      \
    issue_tile(0); issue_tile(1);                                              \
    for (int t = 0; t < KT; t++) {                                             \
        issue_tile(t + 2);                                                     \
        CP_WAIT2();                                                            \
        __syncthreads();                                                       \
        const float* As = sm + (t % NSTAGE) * STAGE_F;                         \
        const float* Bs = As + ATILE;                                          \
        const float* Ap = As + (wm * 64 + lr) * BKP + 8 * lc;                  \
        const float* Bp = Bs + (wn * 64 + lr) * BKP + 8 * lc;                  \
        _Pragma("unroll")                                                      \
        for (int half = 0; half < 2; half++) {                                 \
            float4 af[4][2]; float4 bf[8];                                     \
            _Pragma("unroll")                                                  \
            for (int mi = 0; mi < 4; mi++) {                                   \
                af[mi][0] = *(const float4*)(Ap + mi * 16 * BKP + half * 4);   \
                af[mi][1] = *(const float4*)(Ap + (mi * 16 + 8) * BKP + half * 4); \
            }                                                                  \
            _Pragma("unroll")                                                  \
            for (int ni = 0; ni < 8; ni++)                                     \
                bf[ni] = *(const float4*)(Bp + ni * 8 * BKP + half * 4);       \
            _Pragma("unroll")                                                  \
            for (int j = 0; j < 2; j++) {                                      \
                uint32_t bb[8][2];                                             \
                _Pragma("unroll")                                              \
                for (int ni = 0; ni < 8; ni++) {                               \
                    bb[ni][0] = FU(COMP(bf[ni], 2 * j));                       \
                    bb[ni][1] = FU(COMP(bf[ni], 2 * j + 1));                   \
                }                                                              \
                _Pragma("unroll")                                              \
                for (int mi = 0; mi < 4; mi++) {                               \
                    uint32_t a[4];                                             \
                    a[0] = FU(COMP(af[mi][0], 2 * j));                         \
                    a[1] = FU(COMP(af[mi][1], 2 * j));                         \
                    a[2] = FU(COMP(af[mi][0], 2 * j + 1));                     \
                    a[3] = FU(COMP(af[mi][1], 2 * j + 1));                     \
                    _Pragma("unroll")                                          \
                    for (int ni = 0; ni < 8; ni++)                             \
                        mma8(acc[mi][ni], a, bb[ni]);                          \
                }                                                              \
            }                                                                  \
        }                                                                      \
        __syncthreads();                                                       \
    }

// ---------------------------------------------------------------------------
// GEMM1: Y = g_c @ g_w1^T + b_h   -> g_y
__global__ __launch_bounds__(128)
void gemm1_kernel(const float* __restrict__ bias) {
    extern __shared__ float sm[];
    const int tid = threadIdx.x;
    const int bm = blockIdx.y, bn = blockIdx.x;

    auto issue_tile = [&](int t) {
        if (t < KT1) {
            float* base = sm + (t % NSTAGE) * STAGE_F;
            const float* src = g_c + (size_t)bm * BM * 2688 + t * BK;
            #pragma unroll
            for (int i = 0; i < 8; i++) {
                int idx = tid + i * 128;
                int row = idx >> 3, kc = (idx & 7) * 4;
                cp_async16(base + row * BKP + kc, src + (size_t)row * 2688 + kc);
            }
            const float* ws = g_w1 + (size_t)(bn * BN) * 2688 + t * BK;
            float* bbase = base + ATILE;
            #pragma unroll
            for (int i = 0; i < 8; i++) {
                int idx = tid + i * 128;
                int row = idx >> 3, kc = (idx & 7) * 4;
                cp_async16(bbase + row * BKP + kc, ws + (size_t)row * 2688 + kc);
            }
        }
        CP_COMMIT();
    };

    GEMM_CORE(KT1)

    #pragma unroll
    for (int mi = 0; mi < 4; mi++) {
        #pragma unroll
        for (int ni = 0; ni < 8; ni++) {
            int r0 = bm * BM + wm * 64 + mi * 16 + lr;
            int c0 = bn * BN + wn * 64 + ni * 8 + 2 * lc;
            float b0 = bias[c0], b1 = bias[c0 + 1];
            float2 v0 = make_float2(acc[mi][ni][0] + b0, acc[mi][ni][1] + b1);
            float2 v1 = make_float2(acc[mi][ni][2] + b0, acc[mi][ni][3] + b1);
            *(float2*)&g_y[(size_t)r0 * HID + c0] = v0;
            *(float2*)&g_y[(size_t)(r0 + 8) * HID + c0] = v1;
        }
    }
}

// ---------------------------------------------------------------------------
// GEMM2: U = [g_h | g_c(m part)] @ g_wcat^T + g_bcat  -> g_u
__global__ __launch_bounds__(128)
void gemm2_kernel() {
    extern __shared__ float sm[];
    const int tid = threadIdx.x;
    const int bm = blockIdx.y, bn = blockIdx.x;

    auto issue_tile = [&](int t) {
        if (t < KT2) {
            float* base = sm + (t % NSTAGE) * STAGE_F;
            const float* src; int ld;
            if (t < 32) { src = g_h + (size_t)bm * BM * 1024 + t * BK;                ld = 1024; }
            else        { src = g_c + (size_t)bm * BM * 2688 + 1536 + (t - 32) * BK;  ld = 2688; }
            #pragma unroll
            for (int i = 0; i < 8; i++) {
                int idx = tid + i * 128;
                int row = idx >> 3, kc = (idx & 7) * 4;
                cp_async16(base + row * BKP + kc, src + (size_t)row * ld + kc);
            }
            const float* ws = g_wcat + (size_t)(bn * BN) * 2176 + t * BK;
            float* bbase = base + ATILE;
            #pragma unroll
            for (int i = 0; i < 8; i++) {
                int idx = tid + i * 128;
                int row = idx >> 3, kc = (idx & 7) * 4;
                cp_async16(bbase + row * BKP + kc, ws + (size_t)row * 2176 + kc);
            }
        }
        CP_COMMIT();
    };

    GEMM_CORE(KT2)

    #pragma unroll
    for (int mi = 0; mi < 4; mi++) {
        #pragma unroll
        for (int ni = 0; ni < 8; ni++) {
            int r0 = bm * BM + wm * 64 + mi * 16 + lr;
            int c0 = bn * BN + wn * 64 + ni * 8 + 2 * lc;
            float b0 = g_bcat[c0], b1 = g_bcat[c0 + 1];
            float2 v0 = make_float2(acc[mi][ni][0] + b0, acc[mi][ni][1] + b1);
            float2 v1 = make_float2(acc[mi][ni][2] + b0, acc[mi][ni][3] + b1);
            *(float2*)&g_u[(size_t)r0 * 256 + c0] = v0;
            *(float2*)&g_u[(size_t)(r0 + 8) * 256 + c0] = v1;
        }
    }
}

// ---------------------------------------------------------------------------
// LayerNorm + ReLU over rows of g_y -> hout (exact) and g_h (tf32-rounded)
__global__ __launch_bounds__(256)
void ln_relu_kernel(const float* __restrict__ g, const float* __restrict__ b,
                    float* __restrict__ hout) {
    __shared__ float sa[8], sb[8], smu[2];
    const int row = blockIdx.x, tid = threadIdx.x;
    const int lane = tid & 31, w = tid >> 5;

    float4 v = ((const float4*)(g_y + (size_t)row * HID))[tid];
    float s = v.x + v.y + v.z + v.w;
    float s2 = v.x * v.x + v.y * v.y + v.z * v.z + v.w * v.w;
    #pragma unroll
    for (int o = 16; o; o >>= 1) {
        s  += __shfl_down_sync(0xffffffffu, s, o);
        s2 += __shfl_down_sync(0xffffffffu, s2, o);
    }
    if (!lane) { sa[w] = s; sb[w] = s2; }
    __syncthreads();
    if (w == 0) {
        s  = (lane < 8) ? sa[lane] : 0.f;
        s2 = (lane < 8) ? sb[lane] : 0.f;
        #pragma unroll
        for (int o = 4; o; o >>= 1) {
            s  += __shfl_down_sync(0xffffffffu, s, o);
            s2 += __shfl_down_sync(0xffffffffu, s2, o);
        }
        if (!lane) {
            float mu = s * (1.f / HID);
            float var = s2 * (1.f / HID) - mu * mu;
            smu[0] = mu;
            smu[1] = rsqrtf(var + 1e-5f);
        }
    }
    __syncthreads();
    const float mu = smu[0], inv = smu[1];
    float4 gg = ((const float4*)g)[tid];
    float4 bb = ((const float4*)b)[tid];
    float4 o;
    o.x = fmaxf((v.x - mu) * inv * gg.x + bb.x, 0.f);
    o.y = fmaxf((v.y - mu) * inv * gg.y + bb.y, 0.f);
    o.z = fmaxf((v.z - mu) * inv * gg.z + bb.z, 0.f);
    o.w = fmaxf((v.w - mu) * inv * gg.w + bb.w, 0.f);
    ((float4*)(hout + (size_t)row * HID))[tid] = o;
    float4 orr;
    orr.x = tfr(o.x); orr.y = tfr(o.y); orr.z = tfr(o.z); orr.w = tfr(o.w);
    ((float4*)(g_h + (size_t)row * HID))[tid] = orr;
}

// ---------------------------------------------------------------------------
// Finalize: separable p-norm outer products -> m update
__global__ __launch_bounds__(128)
void finalize_kernel(const float* __restrict__ Mp, float* __restrict__ mout) {
    __shared__ float u[196];
    __shared__ float red[6];
    __shared__ float invn[4];
    __shared__ float cA[24], cB[24];
    const int row = blockIdx.x, tid = threadIdx.x;
    const int w = tid >> 5, lane = tid & 31;

    for (int i = tid; i < 196; i += 128) u[i] = g_u[(size_t)row * 256 + i];
    __syncthreads();

    auto p5 = [](float x) { float a = fabsf(x); float a2 = a * a; return a2 * a2 * a; };

    if (w == 0) {
        float lo = (lane < 24) ? p5(u[4 + lane]) : 0.f;
        float hi = (lane < 24) ? p5(u[4 + 24 + lane]) : 0.f;
        #pragma unroll
        for (int o = 16; o; o >>= 1) {
            lo += __shfl_down_sync(0xffffffffu, lo, o);
            hi += __shfl_down_sync(0xffffffffu, hi, o);
        }
        if (!lane) { red[0] = lo; red[1] = hi; }
    } else if (w == 1) {
        float x = p5(u[4 + 48 + lane]) + ((lane < 16) ? p5(u[4 + 80 + lane]) : 0.f);
        #pragma unroll
        for (int o = 16; o; o >>= 1) x += __shfl_down_sync(0xffffffffu, x, o);
        if (!lane) red[2] = x;
    } else if (w == 2) {
        float lo = (lane < 24) ? p5(u[100 + lane]) : 0.f;
        float hi = (lane < 24) ? p5(u[100 + 24 + lane]) : 0.f;
        #pragma unroll
        for (int o = 16; o; o >>= 1) {
            lo += __shfl_down_sync(0xffffffffu, lo, o);
            hi += __shfl_down_sync(0xffffffffu, hi, o);
        }
        if (!lane) { red[3] = lo; red[4] = hi; }
    } else {
        float x = p5(u[100 + 48 + lane]) + ((lane < 16) ? p5(u[100 + 80 + lane]) : 0.f);
        #pragma unroll
        for (int o = 16; o; o >>= 1) x += __shfl_down_sync(0xffffffffu, x, o);
        if (!lane) red[5] = x;
    }
    __syncthreads();

    if (tid < 4) {
        float s1 = (tid == 0) ? red[0] : (tid == 1) ? red[1] : (tid == 2) ? red[3] : red[4];
        float s2 = (tid < 2) ? red[2] : red[5];
        float nrm = powf(s1 * s2, 0.2f);
        invn[tid] = 1.f / fmaxf(nrm, 1e-12f);
    }
    __syncthreads();

    if (tid < 24) {
        cA[tid] = 0.5f * (u[0] * u[4 + tid] * invn[0] + u[1] * u[4 + 24 + tid] * invn[1]);
    } else if (tid >= 32 && tid < 56) {
        int i = tid - 32;
        cB[i] = 0.5f * (u[2] * u[100 + i] * invn[2] + u[3] * u[100 + 24 + i] * invn[3]);
    }
    __syncthreads();

    const float* mp = Mp + (size_t)row * MEM;
    float* mo = mout + (size_t)row * MEM;
    #pragma unroll
    for (int j = tid; j < MEM; j += 128) {
        int i = j / 48, j2 = j - i * 48;
        mo[j] = mp[j] + cA[i] * u[52 + j2] - cB[i] * u[148 + j2];
    }
}

// ---------------------------------------------------------------------------
extern "C" void kernel_launch(void* const* d_in, const int* in_sizes, int n_in,
                              void* d_out, int out_size) {
    const float* input  = (const float*)d_in[0];
    const float* h_prev = (const float*)d_in[1];
    const float* m_prev = (const float*)d_in[2];
    const float* W_h    = (const float*)d_in[3];
    const float* b_h    = (const float*)d_in[4];
    const float* ln_g   = (const float*)d_in[5];
    const float* ln_b   = (const float*)d_in[6];
    const float* W_a    = (const float*)d_in[7];
    const float* b_a    = (const float*)d_in[8];
    const float* W_b    = (const float*)d_in[9];
    const float* b_b    = (const float*)d_in[10];
    const float* W_va   = (const float*)d_in[11];
    const float* b_va   = (const float*)d_in[12];
    const float* W_vb   = (const float*)d_in[13];
    const float* b_vb   = (const float*)d_in[14];

    float* out  = (float*)d_out;
    float* hout = out;
    float* mout = out + (size_t)Bsz * HID;

    cudaFuncSetAttribute(gemm1_kernel, cudaFuncAttributeMaxDynamicSharedMemorySize, SMEM_BYTES);
    cudaFuncSetAttribute(gemm2_kernel, cudaFuncAttributeMaxDynamicSharedMemorySize, SMEM_BYTES);

    round_concat_kernel<<<43008, 256>>>((const float4*)input, (const float4*)h_prev,
                                        (const float4*)m_prev);
    round_wh_kernel<<<2688, 256>>>((const float4*)W_h);
    pack_w_kernel<<<(196 * 2176 + 255) / 256, 256>>>(W_a, b_a, W_b, b_b, W_va, b_va, W_vb, b_vb);
    gemm1_kernel<<<dim3(HID / BN, Bsz / BM), 128, SMEM_BYTES>>>(b_h);
    ln_relu_kernel<<<Bsz, 256>>>(ln_g, ln_b, hout);
    gemm2_kernel<<<dim3(2, Bsz / BM), 128, SMEM_BYTES>>>();
    finalize_kernel<<<Bsz, 128>>>(m_prev, mout);
}